// round 16
// baseline (speedup 1.0000x reference)
#include <cuda_runtime.h>
#include <cuda_fp16.h>
#include <math.h>
#include <stdint.h>

#define NPTS   32768
#define NEDGE  524288
#define NBATCH 2
#define HID    64
#define LIFTD  256
#define NLAYER 4

// ---------------- scratch ----------------
__device__ float    d_h[NBATCH * NPTS * HID];
__device__ uint32_t d_Ah[NBATCH * NPTS * 32];   // half2-packed A
__device__ uint32_t d_Pdh[NPTS * 32];           // half2-packed Pd
__device__ float    d_agg[NBATCH * NPTS * HID]; // G = sum of gelu (pre-W2)
__device__ float    d_invc[NPTS];
__device__ int      d_deg[NPTS];
__device__ int      d_off[NPTS];
__device__ int      d_cursor[NPTS];
__device__ int      d_ssrc[NEDGE];
__device__ int      d_is64;

__device__ __forceinline__ float gelu_fast(float x) {
    float x2 = x * x;
    float inner = x * fmaf(0.0356774081f, x2, 0.7978845608f);
    float t;
    asm("tanh.approx.f32 %0, %1;" : "=f"(t) : "f"(inner));
    float hx = 0.5f * x;
    return fmaf(hx, t, hx);
}
__device__ __forceinline__ uint32_t gelu_h2(uint32_t xu) {
    __half2 x = *(__half2*)&xu;
    const __half2 c1 = __floats2half2_rn(0.0356774081f, 0.0356774081f);
    const __half2 c0 = __floats2half2_rn(0.7978845608f, 0.7978845608f);
    const __half2 hf = __floats2half2_rn(0.5f, 0.5f);
    __half2 x2 = __hmul2(x, x);
    __half2 inner = __hmul2(x, __hfma2(c1, x2, c0));
    uint32_t tu;
    asm("tanh.approx.f16x2 %0, %1;" : "=r"(tu) : "r"(*(uint32_t*)&inner));
    __half2 hx = __hmul2(hf, x);
    __half2 res = __hfma2(hx, *(__half2*)&tu, hx);
    return *(uint32_t*)&res;
}
__device__ __forceinline__ void mma_fp16(float* d, const uint32_t* a, const uint32_t* b) {
    asm volatile("mma.sync.aligned.m16n8k16.row.col.f32.f16.f16.f32 "
                 "{%0,%1,%2,%3}, {%4,%5,%6,%7}, {%8,%9}, {%0,%1,%2,%3};"
                 : "+f"(d[0]), "+f"(d[1]), "+f"(d[2]), "+f"(d[3])
                 : "r"(a[0]), "r"(a[1]), "r"(a[2]), "r"(a[3]), "r"(b[0]), "r"(b[1]));
}
__device__ __forceinline__ uint32_t pack_h2(float a, float b) {
    __half2 h = __floats2half2_rn(a, b);
    return *(uint32_t*)&h;
}
__device__ __forceinline__ float2 unpack_h2(uint32_t u) {
    return __half22float2(*(__half2*)&u);
}

#define H_STRIDE 36
#define W_STRIDE 72
#define C_STRIDE 68

// ---------------- k_detect ----------------
__global__ void __launch_bounds__(256) k_detect(const void* __restrict__ ei) {
    int t = threadIdx.x;
#pragma unroll
    for (int r = 0; r < 32; r++)
        ((int4*)d_deg)[t + 256 * r] = make_int4(0, 0, 0, 0);
    __shared__ int bad;
    if (t == 0) bad = 0;
    __syncthreads();
    if (t < 128) {
        long long v = ((const long long*)ei)[t];
        if (v < 0 || v >= NPTS) atomicOr(&bad, 1);
    }
    __syncthreads();
    if (t == 0) d_is64 = bad ? 0 : 1;
}

// ---------------- k_count ----------------
__global__ void k_count(const void* __restrict__ ei) {
    int e = blockIdx.x * blockDim.x + threadIdx.x;
    if (e < NEDGE) {
        int dd = d_is64 ? (int)((const long long*)ei)[NEDGE + e]
                        : ((const int*)ei)[NEDGE + e];
        atomicAdd(&d_deg[dd], 1);
    }
}

// ---------------- k_scan ----------------
__global__ void __launch_bounds__(1024) k_scan() {
    __shared__ int wsum[32];
    int t = threadIdx.x, lane = t & 31, warp = t >> 5;
    int base = t * 32;
    int v[32];
    int s = 0;
#pragma unroll
    for (int i = 0; i < 32; i++) { v[i] = d_deg[base + i]; s += v[i]; }
    int sc = s;
#pragma unroll
    for (int o = 1; o < 32; o <<= 1) {
        int n = __shfl_up_sync(0xffffffffu, sc, o);
        if (lane >= o) sc += n;
    }
    if (lane == 31) wsum[warp] = sc;
    __syncthreads();
    if (warp == 0) {
        int ws = wsum[lane];
#pragma unroll
        for (int o = 1; o < 32; o <<= 1) {
            int n = __shfl_up_sync(0xffffffffu, ws, o);
            if (lane >= o) ws += n;
        }
        wsum[lane] = ws;
    }
    __syncthreads();
    int off = (warp > 0 ? wsum[warp - 1] : 0) + (sc - s);
#pragma unroll
    for (int i = 0; i < 32; i++) {
        d_off[base + i] = off;
        d_cursor[base + i] = off;
        d_invc[base + i] = 1.0f / fmaxf((float)v[i], 1.0f);
        off += v[i];
    }
}

// ---------------- k_sortz: src-only CSR fill ----------------
__global__ void __launch_bounds__(256) k_sortz(const void* __restrict__ ei) {
    int e = blockIdx.x * 256 + threadIdx.x;
    int is64 = d_is64;
    int ss, dd;
    if (is64) {
        ss = (int)((const long long*)ei)[e];
        dd = (int)((const long long*)ei)[NEDGE + e];
    } else {
        ss = ((const int*)ei)[e];
        dd = ((const int*)ei)[NEDGE + e];
    }
    int p = atomicAdd(&d_cursor[dd], 1);
    d_ssrc[p] = ss;
}

// ---------------- k_lift: fp16 mma, 128 items/block ----------------
#define LIFT_IN   0
#define LIFT_B2   3072
#define LIFT_TS   3328
#define LIFT_WS   (3328 + 34816)
#define LIFT_SMEM (LIFT_WS + 9216)

__global__ void __launch_bounds__(256) k_lift(
    const float* __restrict__ x, const float* __restrict__ pos,
    const float* __restrict__ w1, const float* __restrict__ b1,
    const float* __restrict__ w2, const float* __restrict__ b2)
{
    extern __shared__ char smem[];
    float*    in_s = (float*)(smem + LIFT_IN);
    float*    b2_s = (float*)(smem + LIFT_B2);
    uint32_t* t_s  = (uint32_t*)(smem + LIFT_TS);
    float*    t_sf = (float*)(smem + LIFT_TS);
    uint32_t* w_s  = (uint32_t*)(smem + LIFT_WS);

    int t = threadIdx.x;
    int item0 = blockIdx.x * 128;

    for (int idx = t; idx < 640; idx += 256) {
        int j = idx / 5, i = idx % 5;
        int item = item0 + j;
        int b = item >> 15, n = item & (NPTS - 1);
        in_s[j * 6 + i] = (i < 3) ? x[((size_t)b * NPTS + n) * 3 + i] : pos[n * 2 + (i - 3)];
    }
    if (t < 64) b2_s[t] = b2[t];
    __syncthreads();

    int c2 = t & 31, jg = t >> 5;
    int w  = t >> 5, lane = t & 31;
    int r  = lane >> 2, c4 = lane & 3;
    int m0 = w * 16;

    float acc[8][4];
#pragma unroll
    for (int j = 0; j < 8; j++)
        acc[j][0] = acc[j][1] = acc[j][2] = acc[j][3] = 0.f;

    for (int ch = 0; ch < 4; ch++) {
        int cc0 = ch * 64 + 2 * c2, cc1 = cc0 + 1;
        float wa0 = w1[cc0], wa1 = w1[LIFTD + cc0], wa2 = w1[2 * LIFTD + cc0];
        float wa3 = w1[3 * LIFTD + cc0], wa4 = w1[4 * LIFTD + cc0];
        float wb0 = w1[cc1], wb1 = w1[LIFTD + cc1], wb2 = w1[2 * LIFTD + cc1];
        float wb3 = w1[3 * LIFTD + cc1], wb4 = w1[4 * LIFTD + cc1];
        float bc0 = b1[cc0], bc1 = b1[cc1];
#pragma unroll 4
        for (int rr = 0; rr < 16; rr++) {
            int row = jg * 16 + rr;
            const float* in = in_s + row * 6;
            float v0 = bc0 + in[0] * wa0 + in[1] * wa1 + in[2] * wa2 + in[3] * wa3 + in[4] * wa4;
            float v1 = bc1 + in[0] * wb0 + in[1] * wb1 + in[2] * wb2 + in[3] * wb3 + in[4] * wb4;
            t_s[row * H_STRIDE + c2] = pack_h2(gelu_fast(v0), gelu_fast(v1));
        }
        for (int idx = t; idx < 2048; idx += 256) {
            int i = idx >> 6, n = idx & 63;
            w_s[i * W_STRIDE + n] = pack_h2(w2[(ch * 64 + 2 * i) * HID + n],
                                            w2[(ch * 64 + 2 * i + 1) * HID + n]);
        }
        __syncthreads();

#pragma unroll
        for (int kk = 0; kk < 4; kk++) {
            uint32_t a[4];
            a[0] = t_s[(m0 + r)     * H_STRIDE + kk * 8 + c4];
            a[1] = t_s[(m0 + r + 8) * H_STRIDE + kk * 8 + c4];
            a[2] = t_s[(m0 + r)     * H_STRIDE + kk * 8 + c4 + 4];
            a[3] = t_s[(m0 + r + 8) * H_STRIDE + kk * 8 + c4 + 4];
#pragma unroll
            for (int j = 0; j < 8; j++) {
                uint32_t bb[2];
                bb[0] = w_s[(kk * 8 + c4)     * W_STRIDE + j * 8 + r];
                bb[1] = w_s[(kk * 8 + c4 + 4) * W_STRIDE + j * 8 + r];
                mma_fp16(acc[j], a, bb);
            }
        }
        __syncthreads();
    }

#pragma unroll
    for (int j = 0; j < 8; j++) {
        int col = j * 8 + c4 * 2;
        float b0 = b2_s[col], b1v = b2_s[col + 1];
        *(float2*)(t_sf + (m0 + r)     * C_STRIDE + col) = make_float2(acc[j][0] + b0, acc[j][1] + b1v);
        *(float2*)(t_sf + (m0 + r + 8) * C_STRIDE + col) = make_float2(acc[j][2] + b0, acc[j][3] + b1v);
    }
    __syncthreads();
    for (int idx = t; idx < 8192; idx += 256) {
        int row = idx >> 6, cc = idx & 63;
        d_h[(size_t)(item0 + row) * 64 + cc] = t_sf[row * C_STRIDE + cc];
    }
}

// ---------------- k_APd: fp16 mma, fused update + Pd + A ------------------
#define APD_POS  0
#define APD_PW   1024
#define APD_KB2  2048
#define APD_HS   2304
#define APD_WS   (2304 + 18432)
#define APD_SMEM (APD_WS + 9216)

__global__ void __launch_bounds__(256) k_APd(
    const float* __restrict__ pos, const float* __restrict__ kW1_l,
    const float* __restrict__ kb1_l, const float* __restrict__ kW2_p,
    const float* __restrict__ kb2_p, int do_upd)
{
    extern __shared__ char smem[];
    float*    pos_s  = (float*)(smem + APD_POS);
    float*    pw_s   = (float*)(smem + APD_PW);
    float*    kb2_s  = (float*)(smem + APD_KB2);
    uint32_t* h_s    = (uint32_t*)(smem + APD_HS);
    uint32_t* w_s    = (uint32_t*)(smem + APD_WS);

    int t = threadIdx.x;
    int item0 = blockIdx.x * 128;
    int w = t >> 5, lane = t & 31;
    int r = lane >> 2, c4 = lane & 3;
    int m0 = w * 16;

    if (t < 256) {
        int j = t >> 1, i = t & 1;
        int n = (item0 + j) & (NPTS - 1);
        pos_s[j * 2 + i] = pos[n * 2 + i];
    }
    if (t < 256) pw_s[t] = kW1_l[t];
    if (do_upd && t < 64) kb2_s[t] = kb2_p[t];

    if (do_upd) {
#pragma unroll 4
        for (int i = 0; i < 16; i++) {
            int row = m0 + i;
            float2 g = *(float2*)(d_agg + (size_t)(item0 + row) * 64 + lane * 2);
            h_s[row * H_STRIDE + lane] = pack_h2(g.x, g.y);
        }
        for (int idx = t; idx < 2048; idx += 256) {
            int i = idx >> 6, n = idx & 63;
            w_s[i * W_STRIDE + n] = pack_h2(kW2_p[(2 * i) * 64 + n], kW2_p[(2 * i + 1) * 64 + n]);
        }
        __syncthreads();

        float acc[8][4];
#pragma unroll
        for (int j = 0; j < 8; j++)
            acc[j][0] = acc[j][1] = acc[j][2] = acc[j][3] = 0.f;
#pragma unroll
        for (int kk = 0; kk < 4; kk++) {
            uint32_t a[4];
            a[0] = h_s[(m0 + r)     * H_STRIDE + kk * 8 + c4];
            a[1] = h_s[(m0 + r + 8) * H_STRIDE + kk * 8 + c4];
            a[2] = h_s[(m0 + r)     * H_STRIDE + kk * 8 + c4 + 4];
            a[3] = h_s[(m0 + r + 8) * H_STRIDE + kk * 8 + c4 + 4];
#pragma unroll
            for (int j = 0; j < 8; j++) {
                uint32_t bb[2];
                bb[0] = w_s[(kk * 8 + c4)     * W_STRIDE + j * 8 + r];
                bb[1] = w_s[(kk * 8 + c4 + 4) * W_STRIDE + j * 8 + r];
                mma_fp16(acc[j], a, bb);
            }
        }
        __syncwarp();

        int nA = (item0 + m0 + r) & (NPTS - 1);
        int nB = (item0 + m0 + r + 8) & (NPTS - 1);
        float iA = d_invc[nA], dA = (float)d_deg[nA];
        float iB = d_invc[nB], dB = (float)d_deg[nB];
        size_t gA = (size_t)(item0 + m0 + r) * 64;
        size_t gB = (size_t)(item0 + m0 + r + 8) * 64;
#pragma unroll
        for (int j = 0; j < 8; j++) {
            int col = j * 8 + c4 * 2;
            float k0 = kb2_s[col], k1 = kb2_s[col + 1];
            float2 hA = *(float2*)(d_h + gA + col);
            float2 hB = *(float2*)(d_h + gB + col);
            float a0 = hA.x + (acc[j][0] + dA * k0) * iA;
            float a1 = hA.y + (acc[j][1] + dA * k1) * iA;
            float b0 = hB.x + (acc[j][2] + dB * k0) * iB;
            float b1 = hB.y + (acc[j][3] + dB * k1) * iB;
            *(float2*)(d_h + gA + col) = make_float2(a0, a1);
            *(float2*)(d_h + gB + col) = make_float2(b0, b1);
            h_s[(m0 + r) * H_STRIDE + j * 4 + c4]     = pack_h2(a0, a1);
            h_s[(m0 + r + 8) * H_STRIDE + j * 4 + c4] = pack_h2(b0, b1);
        }
        __syncthreads();
    } else {
        for (int idx = t; idx < 4096; idx += 256) {
            int row = idx >> 5, c2 = idx & 31;
            float2 hv = *(float2*)(d_h + (size_t)(item0 + row) * 64 + c2 * 2);
            h_s[row * H_STRIDE + c2] = pack_h2(hv.x, hv.y);
        }
    }

    for (int idx = t; idx < 2048; idx += 256) {
        int i = idx >> 6, n = idx & 63;
        w_s[i * W_STRIDE + n] = pack_h2(kW1_l[(4 + 2 * i) * 64 + n], kW1_l[(4 + 2 * i + 1) * 64 + n]);
    }
    __syncthreads();

    if (item0 < NPTS) {
        for (int idx = t; idx < 4096; idx += 256) {
            int row = idx >> 5, c2 = idx & 31;
            int n = item0 + row, c = c2 * 2;
            float p0 = pos_s[row * 2], p1 = pos_s[row * 2 + 1];
            float v0 = kb1_l[c]     + p0 * pw_s[128 + c]     + p1 * pw_s[192 + c];
            float v1 = kb1_l[c + 1] + p0 * pw_s[128 + c + 1] + p1 * pw_s[192 + c + 1];
            d_Pdh[(size_t)n * 32 + c2] = pack_h2(v0, v1);
        }
    }

    float acc[8][4];
#pragma unroll
    for (int j = 0; j < 8; j++)
        acc[j][0] = acc[j][1] = acc[j][2] = acc[j][3] = 0.f;
#pragma unroll
    for (int kk = 0; kk < 4; kk++) {
        uint32_t a[4];
        a[0] = h_s[(m0 + r)     * H_STRIDE + kk * 8 + c4];
        a[1] = h_s[(m0 + r + 8) * H_STRIDE + kk * 8 + c4];
        a[2] = h_s[(m0 + r)     * H_STRIDE + kk * 8 + c4 + 4];
        a[3] = h_s[(m0 + r + 8) * H_STRIDE + kk * 8 + c4 + 4];
#pragma unroll
        for (int j = 0; j < 8; j++) {
            uint32_t bb[2];
            bb[0] = w_s[(kk * 8 + c4)     * W_STRIDE + j * 8 + r];
            bb[1] = w_s[(kk * 8 + c4 + 4) * W_STRIDE + j * 8 + r];
            mma_fp16(acc[j], a, bb);
        }
    }
    __syncwarp();

    float p00 = pos_s[(m0 + r) * 2],     p01 = pos_s[(m0 + r) * 2 + 1];
    float p10 = pos_s[(m0 + r + 8) * 2], p11 = pos_s[(m0 + r + 8) * 2 + 1];
#pragma unroll
    for (int j = 0; j < 8; j++) {
        int col = j * 8 + c4 * 2;
        float w00 = pw_s[col], w01 = pw_s[col + 1];
        float w10 = pw_s[64 + col], w11 = pw_s[64 + col + 1];
        h_s[(m0 + r) * H_STRIDE + j * 4 + c4] =
            pack_h2(acc[j][0] + p00 * w00 + p01 * w10, acc[j][1] + p00 * w01 + p01 * w11);
        h_s[(m0 + r + 8) * H_STRIDE + j * 4 + c4] =
            pack_h2(acc[j][2] + p10 * w00 + p11 * w10, acc[j][3] + p10 * w01 + p11 * w11);
    }
    __syncthreads();
    for (int idx = t; idx < 4096; idx += 256) {
        int row = idx >> 5, cc = idx & 31;
        d_Ah[(size_t)(item0 + row) * 32 + cc] = h_s[row * H_STRIDE + cc];
    }
}

// ---------------- k_edge: CSR 1 node/warp, shfl-batched srcs --------------
__global__ void __launch_bounds__(256) k_edge()
{
    int n = blockIdx.x * 8 + (threadIdx.x >> 5);
    int lane = threadIdx.x & 31;
    const uint32_t* A0 = d_Ah;
    const uint32_t* A1 = d_Ah + (size_t)NPTS * 32;

    int len   = d_deg[n];
    int start = d_off[n];
    uint32_t pd = d_Pdh[(size_t)n * 32 + lane];
    __half2 pdh = *(__half2*)&pd;
    float a00 = 0.f, a01 = 0.f, a10 = 0.f, a11 = 0.f;

    for (int base = 0; base < len; base += 32) {
        int cnt = min(32, len - base);
        int my_src = (lane < cnt) ? __ldg(&d_ssrc[start + base + lane]) : 0;
#pragma unroll 4
        for (int e = 0; e < cnt; e++) {
            int ss = __shfl_sync(0xffffffffu, my_src, e);
            uint32_t av0 = __ldg(&A0[(size_t)ss * 32 + lane]);
            uint32_t av1 = __ldg(&A1[(size_t)ss * 32 + lane]);
            __half2 s0 = __hadd2(*(__half2*)&av0, pdh);
            __half2 s1 = __hadd2(*(__half2*)&av1, pdh);
            float2 f0 = unpack_h2(gelu_h2(*(uint32_t*)&s0));
            float2 f1 = unpack_h2(gelu_h2(*(uint32_t*)&s1));
            a00 += f0.x; a01 += f0.y; a10 += f1.x; a11 += f1.y;
        }
    }
    *(float2*)(d_agg + (size_t)n * 64 + lane * 2) = make_float2(a00, a01);
    *(float2*)(d_agg + (size_t)(NPTS + n) * 64 + lane * 2) = make_float2(a10, a11);
}

// ---------------- k_proj: fp16 mma, fused update + proj MLP ---------------
#define PROJ_HS   0
#define PROJ_WS   18432
#define PROJ_W2   (18432 + 9216)
#define PROJ_B1   (PROJ_W2 + 1024)
#define PROJ_KB2  (PROJ_B1 + 1024)
#define PROJ_SMEM (PROJ_KB2 + 256)

__global__ void __launch_bounds__(256) k_proj(
    const float* __restrict__ w1, const float* __restrict__ b1,
    const float* __restrict__ w2, const float* __restrict__ b2,
    const float* __restrict__ kW2_p, const float* __restrict__ kb2_p,
    float* __restrict__ out)
{
    extern __shared__ char smem[];
    uint32_t* h_s   = (uint32_t*)(smem + PROJ_HS);
    uint32_t* w_s   = (uint32_t*)(smem + PROJ_WS);
    float*    w2_s  = (float*)(smem + PROJ_W2);
    float*    b1_s  = (float*)(smem + PROJ_B1);
    float*    kb2_s = (float*)(smem + PROJ_KB2);

    int t = threadIdx.x;
    int item0 = blockIdx.x * 128;
    int w = t >> 5, lane = t & 31;
    int r = lane >> 2, c4 = lane & 3;
    int m0 = w * 16;

    w2_s[t] = w2[t];
    b1_s[t] = b1[t];
    if (t < 64) kb2_s[t] = kb2_p[t];

#pragma unroll 4
    for (int i = 0; i < 16; i++) {
        int row = m0 + i;
        float2 g = *(float2*)(d_agg + (size_t)(item0 + row) * 64 + lane * 2);
        h_s[row * H_STRIDE + lane] = pack_h2(g.x, g.y);
    }
    for (int idx = t; idx < 2048; idx += 256) {
        int i = idx >> 6, n = idx & 63;
        w_s[i * W_STRIDE + n] = pack_h2(kW2_p[(2 * i) * 64 + n], kW2_p[(2 * i + 1) * 64 + n]);
    }
    __syncthreads();

    {
        float acc[8][4];
#pragma unroll
        for (int j = 0; j < 8; j++)
            acc[j][0] = acc[j][1] = acc[j][2] = acc[j][3] = 0.f;
#pragma unroll
        for (int kk = 0; kk < 4; kk++) {
            uint32_t a[4];
            a[0] = h_s[(m0 + r)     * H_STRIDE + kk * 8 + c4];
            a[1] = h_s[(m0 + r + 8) * H_STRIDE + kk * 8 + c4];
            a[2] = h_s[(m0 + r)     * H_STRIDE + kk * 8 + c4 + 4];
            a[3] = h_s[(m0 + r + 8) * H_STRIDE + kk * 8 + c4 + 4];
#pragma unroll
            for (int j = 0; j < 8; j++) {
                uint32_t bb[2];
                bb[0] = w_s[(kk * 8 + c4)     * W_STRIDE + j * 8 + r];
                bb[1] = w_s[(kk * 8 + c4 + 4) * W_STRIDE + j * 8 + r];
                mma_fp16(acc[j], a, bb);
            }
        }
        __syncwarp();

        int nA = (item0 + m0 + r) & (NPTS - 1);
        int nB = (item0 + m0 + r + 8) & (NPTS - 1);
        float iA = d_invc[nA], dA = (float)d_deg[nA];
        float iB = d_invc[nB], dB = (float)d_deg[nB];
        size_t gA = (size_t)(item0 + m0 + r) * 64;
        size_t gB = (size_t)(item0 + m0 + r + 8) * 64;
#pragma unroll
        for (int j = 0; j < 8; j++) {
            int col = j * 8 + c4 * 2;
            float k0 = kb2_s[col], k1 = kb2_s[col + 1];
            float2 hA = *(float2*)(d_h + gA + col);
            float2 hB = *(float2*)(d_h + gB + col);
            h_s[(m0 + r) * H_STRIDE + j * 4 + c4] =
                pack_h2(hA.x + (acc[j][0] + dA * k0) * iA, hA.y + (acc[j][1] + dA * k1) * iA);
            h_s[(m0 + r + 8) * H_STRIDE + j * 4 + c4] =
                pack_h2(hB.x + (acc[j][2] + dB * k0) * iB, hB.y + (acc[j][3] + dB * k1) * iB);
        }
        __syncwarp();
    }

    uint32_t a[4][4];
#pragma unroll
    for (int kk = 0; kk < 4; kk++) {
        a[kk][0] = h_s[(m0 + r)     * H_STRIDE + kk * 8 + c4];
        a[kk][1] = h_s[(m0 + r + 8) * H_STRIDE + kk * 8 + c4];
        a[kk][2] = h_s[(m0 + r)     * H_STRIDE + kk * 8 + c4 + 4];
        a[kk][3] = h_s[(m0 + r + 8) * H_STRIDE + kk * 8 + c4 + 4];
    }

    float sum0 = 0.f, sum1 = 0.f;
    for (int ch = 0; ch < 4; ch++) {
        __syncthreads();
        for (int idx = t; idx < 2048; idx += 256) {
            int i = idx >> 6, n = idx & 63;
            w_s[i * W_STRIDE + n] = pack_h2(w1[(2 * i) * 256 + ch * 64 + n],
                                            w1[(2 * i + 1) * 256 + ch * 64 + n]);
        }
        __syncthreads();

        float acc[8][4];
#pragma unroll
        for (int j = 0; j < 8; j++)
            acc[j][0] = acc[j][1] = acc[j][2] = acc[j][3] = 0.f;
#pragma unroll
        for (int kk = 0; kk < 4; kk++) {
#pragma unroll
            for (int j = 0; j < 8; j++) {
                uint32_t bb[2];
                bb[0] = w_s[(kk * 8 + c4)     * W_STRIDE + j * 8 + r];
                bb[1] = w_s[(kk * 8 + c4 + 4) * W_STRIDE + j * 8 + r];
                mma_fp16(acc[j], a[kk], bb);
            }
        }
#pragma unroll
        for (int j = 0; j < 8; j++) {
            int col = ch * 64 + j * 8 + c4 * 2;
            sum0 += gelu_fast(acc[j][0] + b1_s[col]) * w2_s[col]
                  + gelu_fast(acc[j][1] + b1_s[col + 1]) * w2_s[col + 1];
            sum1 += gelu_fast(acc[j][2] + b1_s[col]) * w2_s[col]
                  + gelu_fast(acc[j][3] + b1_s[col + 1]) * w2_s[col + 1];
        }
    }

    sum0 += __shfl_xor_sync(0xffffffffu, sum0, 1);
    sum0 += __shfl_xor_sync(0xffffffffu, sum0, 2);
    sum1 += __shfl_xor_sync(0xffffffffu, sum1, 1);
    sum1 += __shfl_xor_sync(0xffffffffu, sum1, 2);
    if (c4 == 0) {
        float bb = b2[0];
        out[item0 + m0 + r]     = sum0 + bb;
        out[item0 + m0 + r + 8] = sum1 + bb;
    }
}

// ---------------- launch ----------------
extern "C" void kernel_launch(void* const* d_in, const int* in_sizes, int n_in,
                              void* d_out, int out_size) {
    (void)in_sizes; (void)n_in; (void)out_size;
    const float* x    = (const float*)d_in[0];
    const float* pos  = (const float*)d_in[1];
    const void*  ei   = d_in[2];
    const float* lw1  = (const float*)d_in[3];
    const float* lb1  = (const float*)d_in[4];
    const float* lw2  = (const float*)d_in[5];
    const float* lb2  = (const float*)d_in[6];
    const float* kW1  = (const float*)d_in[7];
    const float* kb1  = (const float*)d_in[8];
    const float* kW2  = (const float*)d_in[9];
    const float* kb2  = (const float*)d_in[10];
    const float* pw1  = (const float*)d_in[11];
    const float* pb1  = (const float*)d_in[12];
    const float* pw2  = (const float*)d_in[13];
    const float* pb2  = (const float*)d_in[14];
    float* out = (float*)d_out;

    cudaFuncSetAttribute(k_lift, cudaFuncAttributeMaxDynamicSharedMemorySize, LIFT_SMEM);
    cudaFuncSetAttribute(k_APd,  cudaFuncAttributeMaxDynamicSharedMemorySize, APD_SMEM);
    cudaFuncSetAttribute(k_proj, cudaFuncAttributeMaxDynamicSharedMemorySize, PROJ_SMEM);

    k_detect<<<1, 256>>>(ei);                                                       // 0
    k_count<<<NEDGE / 256, 256>>>(ei);                                              // 1
    k_lift<<<(NBATCH * NPTS) / 128, 256, LIFT_SMEM>>>(x, pos, lw1, lb1, lw2, lb2);  // 2
    k_APd<<<(NBATCH * NPTS) / 128, 256, APD_SMEM>>>(pos, kW1, kb1, kW2, kb2, 0);    // 3
    k_scan<<<1, 1024>>>();                                                          // 4
    k_sortz<<<NEDGE / 256, 256>>>(ei);                                              // 5
    k_edge<<<NPTS / 8, 256>>>();                                                    // 6

    for (int l = 1; l < NLAYER; l++) {
        const float* W1l = kW1 + (size_t)l * 68 * 64;
        const float* b1l = kb1 + (size_t)l * 64;
        const float* W2p = kW2 + (size_t)(l - 1) * 64 * 64;
        const float* b2p = kb2 + (size_t)(l - 1) * 64;
        k_APd<<<(NBATCH * NPTS) / 128, 256, APD_SMEM>>>(pos, W1l, b1l, W2p, b2p, 1);
        k_edge<<<NPTS / 8, 256>>>();
    }

    k_proj<<<(NBATCH * NPTS) / 128, 256, PROJ_SMEM>>>(
        pw1, pb1, pw2, pb2,
        kW2 + (size_t)(NLAYER - 1) * 64 * 64, kb2 + (size_t)(NLAYER - 1) * 64, out);
}